// round 2
// baseline (speedup 1.0000x reference)
#include <cuda_runtime.h>

#define D_MODEL 1024
#define NHEAD   16
#define DH      64
#define BATCH   4
#define SEQ     2048
#define M_TOT   (BATCH * SEQ)   // 8192

// Scratch (allocation-free rule: __device__ globals)
__device__ float g_v[M_TOT * D_MODEL];     // 32 MB
__device__ float g_attn[M_TOT * D_MODEL];  // 32 MB

// ---------------------------------------------------------------------------
// GEMM: C[M,N] = A[M,K] @ W[N,K]^T + bias[N]
// BM=BN=64, BK=16, 256 threads, each computes a 4x4 microtile.
// Smem staged transposed (As[BK][BM]) so compute reads are float4 / broadcast.
// ---------------------------------------------------------------------------
#define GBM 64
#define GBN 64
#define GBK 16

__global__ __launch_bounds__(256)
void gemm_bias_kernel(const float* __restrict__ A, const float* __restrict__ W,
                      const float* __restrict__ bias, float* __restrict__ C,
                      int M, int N, int K) {
    __shared__ __align__(16) float As[GBK][GBM];
    __shared__ __align__(16) float Ws[GBK][GBN];

    const int tid = threadIdx.x;
    const int tx = tid & 15;        // 0..15 -> output col group
    const int ty = tid >> 4;        // 0..15 -> output row group
    const int row0 = blockIdx.y * GBM;
    const int col0 = blockIdx.x * GBN;

    float acc[4][4];
#pragma unroll
    for (int i = 0; i < 4; i++)
#pragma unroll
        for (int j = 0; j < 4; j++) acc[i][j] = 0.0f;

    // Tile-load mapping: 64 rows x 16 k, 256 threads -> each thread one float4
    const int lr = tid >> 2;          // 0..63 tile row
    const int lk = (tid & 3) * 4;     // 0,4,8,12

    for (int k0 = 0; k0 < K; k0 += GBK) {
        float4 a = *(const float4*)&A[(size_t)(row0 + lr) * K + k0 + lk];
        float4 w = *(const float4*)&W[(size_t)(col0 + lr) * K + k0 + lk];
        As[lk + 0][lr] = a.x; As[lk + 1][lr] = a.y;
        As[lk + 2][lr] = a.z; As[lk + 3][lr] = a.w;
        Ws[lk + 0][lr] = w.x; Ws[lk + 1][lr] = w.y;
        Ws[lk + 2][lr] = w.z; Ws[lk + 3][lr] = w.w;
        __syncthreads();

#pragma unroll
        for (int kk = 0; kk < GBK; kk++) {
            float4 av = *(const float4*)&As[kk][ty * 4];
            float4 wv = *(const float4*)&Ws[kk][tx * 4];
            float ar[4] = {av.x, av.y, av.z, av.w};
            float wr[4] = {wv.x, wv.y, wv.z, wv.w};
#pragma unroll
            for (int i = 0; i < 4; i++)
#pragma unroll
                for (int j = 0; j < 4; j++)
                    acc[i][j] = fmaf(ar[i], wr[j], acc[i][j]);
        }
        __syncthreads();
    }

    float4 bv = *(const float4*)&bias[col0 + tx * 4];
    float br[4] = {bv.x, bv.y, bv.z, bv.w};
#pragma unroll
    for (int i = 0; i < 4; i++) {
        float4 out;
        out.x = acc[i][0] + br[0];
        out.y = acc[i][1] + br[1];
        out.z = acc[i][2] + br[2];
        out.w = acc[i][3] + br[3];
        *(float4*)&C[(size_t)(row0 + ty * 4 + i) * N + col0 + tx * 4] = out;
    }
}

// ---------------------------------------------------------------------------
// Flash attention with q = k = v (shared-QKV). One block = 128 query rows of
// one (batch, head). Each thread owns one query row: q[64] + acc[64] in regs.
// Key/value tiles (identical data!) streamed once through smem.
// Scores staged in smem [j][tid] (lane == bank, conflict-free).
// ---------------------------------------------------------------------------
#define FBM 128   // query rows per block == threads
#define FBN 64    // key tile

__global__ __launch_bounds__(FBM)
void flash_attn_kernel(const float* __restrict__ V, float* __restrict__ O) {
    __shared__ __align__(16) float kv[FBN][DH];   // 16 KB
    __shared__ float sS[FBN * FBM];               // 32 KB

    const int tid   = threadIdx.x;
    const int qrow  = blockIdx.x * FBM + tid;
    const int head  = blockIdx.y;
    const int batch = blockIdx.z;

    const float* vb = V + (size_t)batch * SEQ * D_MODEL + head * DH;

    float q[DH];
#pragma unroll
    for (int d = 0; d < DH; d += 4) {
        float4 t = *(const float4*)&vb[(size_t)qrow * D_MODEL + d];
        q[d] = t.x; q[d + 1] = t.y; q[d + 2] = t.z; q[d + 3] = t.w;
    }

    float m = -1e30f, l = 0.0f;
    float acc[DH];
#pragma unroll
    for (int d = 0; d < DH; d++) acc[d] = 0.0f;

    const float scale = 0.125f;  // 1/sqrt(64)

    for (int kt = 0; kt < SEQ; kt += FBN) {
        __syncthreads();
        // cooperative tile load: 64 rows x 64 f32; 2 threads/row, 8 float4 each
        {
            const int j = tid >> 1;
            const int dbase = (tid & 1) * 32;
            const float4* src = (const float4*)&vb[(size_t)(kt + j) * D_MODEL + dbase];
            float4* dst = (float4*)&kv[j][dbase];
#pragma unroll
            for (int i = 0; i < 8; i++) dst[i] = src[i];
        }
        __syncthreads();

        // scores
        float tmax = -1e30f;
#pragma unroll 4
        for (int j = 0; j < FBN; j++) {
            float s = 0.0f;
#pragma unroll
            for (int d = 0; d < DH; d += 4) {
                float4 kj = *(const float4*)&kv[j][d];
                s = fmaf(q[d], kj.x, s);
                s = fmaf(q[d + 1], kj.y, s);
                s = fmaf(q[d + 2], kj.z, s);
                s = fmaf(q[d + 3], kj.w, s);
            }
            s *= scale;
            sS[j * FBM + tid] = s;
            tmax = fmaxf(tmax, s);
        }

        const float mnew  = fmaxf(m, tmax);
        const float alpha = __expf(m - mnew);
        l *= alpha;
#pragma unroll
        for (int d = 0; d < DH; d++) acc[d] *= alpha;

#pragma unroll 2
        for (int j = 0; j < FBN; j++) {
            float p = __expf(sS[j * FBM + tid] - mnew);
            l += p;
#pragma unroll
            for (int d = 0; d < DH; d += 4) {
                float4 kj = *(const float4*)&kv[j][d];
                acc[d]     = fmaf(p, kj.x, acc[d]);
                acc[d + 1] = fmaf(p, kj.y, acc[d + 1]);
                acc[d + 2] = fmaf(p, kj.z, acc[d + 2]);
                acc[d + 3] = fmaf(p, kj.w, acc[d + 3]);
            }
        }
        m = mnew;
    }

    const float inv = 1.0f / l;
    float* ob = O + ((size_t)batch * SEQ + qrow) * D_MODEL + head * DH;
#pragma unroll
    for (int d = 0; d < DH; d += 4) {
        float4 out;
        out.x = acc[d] * inv;
        out.y = acc[d + 1] * inv;
        out.z = acc[d + 2] * inv;
        out.w = acc[d + 3] * inv;
        *(float4*)&ob[d] = out;
    }
}

// ---------------------------------------------------------------------------
// Launch: v = x@v_w^T + v_b  ->  flash attn (q=k=v)  ->  out@o_w^T + o_b
// ---------------------------------------------------------------------------
extern "C" void kernel_launch(void* const* d_in, const int* in_sizes, int n_in,
                              void* d_out, int out_size) {
    const float* x   = (const float*)d_in[0];
    const float* v_w = (const float*)d_in[1];
    const float* v_b = (const float*)d_in[2];
    const float* o_w = (const float*)d_in[3];
    const float* o_b = (const float*)d_in[4];
    float* out = (float*)d_out;

    float* dv;
    float* da;
    cudaGetSymbolAddress((void**)&dv, g_v);
    cudaGetSymbolAddress((void**)&da, g_attn);

    dim3 ggrid(D_MODEL / GBN, M_TOT / GBM);  // (16, 128)
    gemm_bias_kernel<<<ggrid, 256>>>(x, v_w, v_b, dv, M_TOT, D_MODEL, D_MODEL);

    dim3 agrid(SEQ / FBM, NHEAD, BATCH);     // (16, 16, 4)
    flash_attn_kernel<<<agrid, FBM>>>(dv, da);

    gemm_bias_kernel<<<ggrid, 256>>>(da, o_w, o_b, out, M_TOT, D_MODEL, D_MODEL);
}

// round 3
// speedup vs baseline: 1.9808x; 1.9808x over previous
#include <cuda_runtime.h>

#define D_MODEL 1024
#define NHEAD   16
#define DH      64
#define BATCH   4
#define SEQ     2048
#define M_TOT   (BATCH * SEQ)   // 8192

// Scratch (allocation-free rule: __device__ globals)
__device__ float g_v[M_TOT * D_MODEL];     // 32 MB
__device__ float g_attn[M_TOT * D_MODEL];  // 32 MB

// ---------------------------------------------------------------------------
// GEMM: C[M,N] = A[M,K] @ W[N,K]^T + bias[N]   (unchanged fp32 from R1)
// ---------------------------------------------------------------------------
#define GBM 64
#define GBN 64
#define GBK 16

__global__ __launch_bounds__(256)
void gemm_bias_kernel(const float* __restrict__ A, const float* __restrict__ W,
                      const float* __restrict__ bias, float* __restrict__ C,
                      int M, int N, int K) {
    __shared__ __align__(16) float As[GBK][GBM];
    __shared__ __align__(16) float Ws[GBK][GBN];

    const int tid = threadIdx.x;
    const int tx = tid & 15;
    const int ty = tid >> 4;
    const int row0 = blockIdx.y * GBM;
    const int col0 = blockIdx.x * GBN;

    float acc[4][4];
#pragma unroll
    for (int i = 0; i < 4; i++)
#pragma unroll
        for (int j = 0; j < 4; j++) acc[i][j] = 0.0f;

    const int lr = tid >> 2;
    const int lk = (tid & 3) * 4;

    for (int k0 = 0; k0 < K; k0 += GBK) {
        float4 a = *(const float4*)&A[(size_t)(row0 + lr) * K + k0 + lk];
        float4 w = *(const float4*)&W[(size_t)(col0 + lr) * K + k0 + lk];
        As[lk + 0][lr] = a.x; As[lk + 1][lr] = a.y;
        As[lk + 2][lr] = a.z; As[lk + 3][lr] = a.w;
        Ws[lk + 0][lr] = w.x; Ws[lk + 1][lr] = w.y;
        Ws[lk + 2][lr] = w.z; Ws[lk + 3][lr] = w.w;
        __syncthreads();

#pragma unroll
        for (int kk = 0; kk < GBK; kk++) {
            float4 av = *(const float4*)&As[kk][ty * 4];
            float4 wv = *(const float4*)&Ws[kk][tx * 4];
            float ar[4] = {av.x, av.y, av.z, av.w};
            float wr[4] = {wv.x, wv.y, wv.z, wv.w};
#pragma unroll
            for (int i = 0; i < 4; i++)
#pragma unroll
                for (int j = 0; j < 4; j++)
                    acc[i][j] = fmaf(ar[i], wr[j], acc[i][j]);
        }
        __syncthreads();
    }

    float4 bv = *(const float4*)&bias[col0 + tx * 4];
    float br[4] = {bv.x, bv.y, bv.z, bv.w};
#pragma unroll
    for (int i = 0; i < 4; i++) {
        float4 out;
        out.x = acc[i][0] + br[0];
        out.y = acc[i][1] + br[1];
        out.z = acc[i][2] + br[2];
        out.w = acc[i][3] + br[3];
        *(float4*)&C[(size_t)(row0 + ty * 4 + i) * N + col0 + tx * 4] = out;
    }
}

// ---------------------------------------------------------------------------
// Flash attention, tf32 mma.sync tensor cores. q = k = v.
// Block: 4 warps = 128 thr. Tile: BM=64 queries x BN=64 keys, dh=64.
// Warp w owns query rows 16w..16w+15. KV tile (tf32-rounded fp32) in smem
// serves as BOTH K (for S=Q K^T) and V (for O += P V).
// P staged per-warp in smem as tf32 bits (only __syncwarp needed).
// ---------------------------------------------------------------------------
#define KVS 72   // kv row stride in words (pad: PV B-frags conflict-free)
#define PS  72   // sP row stride in words (STS.64 conflict-free per half-warp)

__device__ __forceinline__ unsigned f2tf(float x) {
    unsigned r;
    asm("cvt.rna.tf32.f32 %0, %1;" : "=r"(r) : "f"(x));
    return r;
}

__device__ __forceinline__ void mma8(float* c, const unsigned* a, unsigned b0, unsigned b1) {
    asm volatile(
        "mma.sync.aligned.m16n8k8.row.col.f32.tf32.tf32.f32 "
        "{%0,%1,%2,%3}, {%4,%5,%6,%7}, {%8,%9}, {%0,%1,%2,%3};\n"
        : "+f"(c[0]), "+f"(c[1]), "+f"(c[2]), "+f"(c[3])
        : "r"(a[0]), "r"(a[1]), "r"(a[2]), "r"(a[3]), "r"(b0), "r"(b1));
}

__global__ __launch_bounds__(128)
void flash_attn_tc(const float* __restrict__ V, float* __restrict__ O) {
    __shared__ __align__(16) float    kv[64 * KVS];        // 18 KB
    __shared__ __align__(16) unsigned sP[4 * 16 * PS];     // 18 KB

    const int tid = threadIdx.x;
    const int w  = tid >> 5;
    const int l  = tid & 31;
    const int lq = l >> 2;   // groupID  (row within mma tile)
    const int li = l & 3;    // threadID_in_group
    const int qt = blockIdx.x;
    const int h  = blockIdx.y;
    const int b  = blockIdx.z;

    const float* vb = V + (size_t)b * SEQ * D_MODEL + h * DH;

    // ---- load Q tile (rows qt*64..+63) scaled by 1/8 (exact), tf32-rounded
    {
        const int r  = tid >> 1;
        const int c0 = (tid & 1) * 32;
        const float4* src = (const float4*)&vb[(size_t)(qt * 64 + r) * D_MODEL + c0];
#pragma unroll
        for (int i = 0; i < 8; i++) {
            float4 t = src[i];
            float4 o;
            o.x = __uint_as_float(f2tf(t.x * 0.125f));
            o.y = __uint_as_float(f2tf(t.y * 0.125f));
            o.z = __uint_as_float(f2tf(t.z * 0.125f));
            o.w = __uint_as_float(f2tf(t.w * 0.125f));
            *(float4*)&kv[r * KVS + c0 + i * 4] = o;
        }
    }
    __syncthreads();

    // ---- build register-resident Q fragments (A of m16n8k8, row-major)
    unsigned qf[8][4];
    {
        const int r0 = w * 16 + lq;
#pragma unroll
        for (int kc = 0; kc < 8; kc++) {
            qf[kc][0] = __float_as_uint(kv[(r0    ) * KVS + kc * 8 + li    ]);
            qf[kc][1] = __float_as_uint(kv[(r0 + 8) * KVS + kc * 8 + li    ]);
            qf[kc][2] = __float_as_uint(kv[(r0    ) * KVS + kc * 8 + li + 4]);
            qf[kc][3] = __float_as_uint(kv[(r0 + 8) * KVS + kc * 8 + li + 4]);
        }
    }

    float of[8][4];
#pragma unroll
    for (int j = 0; j < 8; j++) { of[j][0] = of[j][1] = of[j][2] = of[j][3] = 0.0f; }
    float m_lo = -1e30f, m_hi = -1e30f, l_lo = 0.0f, l_hi = 0.0f;

    unsigned* pw = &sP[w * 16 * PS];   // warp-private P slab

    for (int kt = 0; kt < SEQ; kt += 64) {
        __syncthreads();   // prior tile's reads (incl. Q-frag build) done before overwrite
        // ---- load KV tile (tf32-rounded, unscaled)
        {
            const int r  = tid >> 1;
            const int c0 = (tid & 1) * 32;
            const float4* src = (const float4*)&vb[(size_t)(kt + r) * D_MODEL + c0];
#pragma unroll
            for (int i = 0; i < 8; i++) {
                float4 t = src[i];
                float4 o;
                o.x = __uint_as_float(f2tf(t.x));
                o.y = __uint_as_float(f2tf(t.y));
                o.z = __uint_as_float(f2tf(t.z));
                o.w = __uint_as_float(f2tf(t.w));
                *(float4*)&kv[r * KVS + c0 + i * 4] = o;
            }
        }
        __syncthreads();

        // ---- S = Q K^T (pre-scaled).  B[k][n] = K[n][k] = kv[n][k]
        float sc[8][4];
#pragma unroll
        for (int j = 0; j < 8; j++) { sc[j][0] = sc[j][1] = sc[j][2] = sc[j][3] = 0.0f; }
#pragma unroll
        for (int kc = 0; kc < 8; kc++) {
#pragma unroll
            for (int j = 0; j < 8; j++) {
                unsigned b0 = __float_as_uint(kv[(j * 8 + lq) * KVS + kc * 8 + li    ]);
                unsigned b1 = __float_as_uint(kv[(j * 8 + lq) * KVS + kc * 8 + li + 4]);
                mma8(sc[j], qf[kc], b0, b1);
            }
        }

        // ---- online softmax (rows lq -> c0/c1, lq+8 -> c2/c3)
        float mx_lo = -1e30f, mx_hi = -1e30f;
#pragma unroll
        for (int j = 0; j < 8; j++) {
            mx_lo = fmaxf(mx_lo, fmaxf(sc[j][0], sc[j][1]));
            mx_hi = fmaxf(mx_hi, fmaxf(sc[j][2], sc[j][3]));
        }
        mx_lo = fmaxf(mx_lo, __shfl_xor_sync(0xffffffffu, mx_lo, 1));
        mx_lo = fmaxf(mx_lo, __shfl_xor_sync(0xffffffffu, mx_lo, 2));
        mx_hi = fmaxf(mx_hi, __shfl_xor_sync(0xffffffffu, mx_hi, 1));
        mx_hi = fmaxf(mx_hi, __shfl_xor_sync(0xffffffffu, mx_hi, 2));

        const float mn_lo = fmaxf(m_lo, mx_lo);
        const float mn_hi = fmaxf(m_hi, mx_hi);
        const float al = __expf(m_lo - mn_lo);
        const float ah = __expf(m_hi - mn_hi);
#pragma unroll
        for (int j = 0; j < 8; j++) {
            of[j][0] *= al; of[j][1] *= al;
            of[j][2] *= ah; of[j][3] *= ah;
        }

        float sl = 0.0f, sh = 0.0f;
#pragma unroll
        for (int j = 0; j < 8; j++) {
            sc[j][0] = __expf(sc[j][0] - mn_lo);
            sc[j][1] = __expf(sc[j][1] - mn_lo);
            sc[j][2] = __expf(sc[j][2] - mn_hi);
            sc[j][3] = __expf(sc[j][3] - mn_hi);
            sl += sc[j][0] + sc[j][1];
            sh += sc[j][2] + sc[j][3];
        }
        sl += __shfl_xor_sync(0xffffffffu, sl, 1);
        sl += __shfl_xor_sync(0xffffffffu, sl, 2);
        sh += __shfl_xor_sync(0xffffffffu, sh, 1);
        sh += __shfl_xor_sync(0xffffffffu, sh, 2);
        l_lo = l_lo * al + sl;
        l_hi = l_hi * ah + sh;
        m_lo = mn_lo;
        m_hi = mn_hi;

        // ---- stage P (tf32 bits) in warp-private smem
        __syncwarp();   // WAR: prior PV A-frag reads done before overwrite
#pragma unroll
        for (int j = 0; j < 8; j++) {
            uint2 v0 = make_uint2(f2tf(sc[j][0]), f2tf(sc[j][1]));
            uint2 v1 = make_uint2(f2tf(sc[j][2]), f2tf(sc[j][3]));
            *(uint2*)&pw[(lq    ) * PS + j * 8 + 2 * li] = v0;
            *(uint2*)&pw[(lq + 8) * PS + j * 8 + 2 * li] = v1;
        }
        __syncwarp();

        // ---- O += P V.  A = P (row-major, k=key), B[k][n] = V[key][d] = kv[key][d]
#pragma unroll
        for (int kc = 0; kc < 8; kc++) {
            unsigned af[4];
            af[0] = pw[(lq    ) * PS + kc * 8 + li    ];
            af[1] = pw[(lq + 8) * PS + kc * 8 + li    ];
            af[2] = pw[(lq    ) * PS + kc * 8 + li + 4];
            af[3] = pw[(lq + 8) * PS + kc * 8 + li + 4];
#pragma unroll
            for (int j = 0; j < 8; j++) {
                unsigned b0 = __float_as_uint(kv[(kc * 8 + li    ) * KVS + j * 8 + lq]);
                unsigned b1 = __float_as_uint(kv[(kc * 8 + li + 4) * KVS + j * 8 + lq]);
                mma8(of[j], af, b0, b1);
            }
        }
    }

    // ---- epilogue: normalize and write
    const float il_lo = 1.0f / l_lo;
    const float il_hi = 1.0f / l_hi;
    float* ob = O + ((size_t)b * SEQ + qt * 64) * D_MODEL + h * DH;
    const int r0 = w * 16 + lq;
#pragma unroll
    for (int j = 0; j < 8; j++) {
        float2 v0 = make_float2(of[j][0] * il_lo, of[j][1] * il_lo);
        float2 v1 = make_float2(of[j][2] * il_hi, of[j][3] * il_hi);
        *(float2*)&ob[(size_t)(r0    ) * D_MODEL + j * 8 + 2 * li] = v0;
        *(float2*)&ob[(size_t)(r0 + 8) * D_MODEL + j * 8 + 2 * li] = v1;
    }
}

// ---------------------------------------------------------------------------
// Launch: v = x@v_w^T + v_b  ->  flash attn tf32 (q=k=v)  ->  out@o_w^T + o_b
// ---------------------------------------------------------------------------
extern "C" void kernel_launch(void* const* d_in, const int* in_sizes, int n_in,
                              void* d_out, int out_size) {
    const float* x   = (const float*)d_in[0];
    const float* v_w = (const float*)d_in[1];
    const float* v_b = (const float*)d_in[2];
    const float* o_w = (const float*)d_in[3];
    const float* o_b = (const float*)d_in[4];
    float* out = (float*)d_out;

    float* dv;
    float* da;
    cudaGetSymbolAddress((void**)&dv, g_v);
    cudaGetSymbolAddress((void**)&da, g_attn);

    dim3 ggrid(D_MODEL / GBN, M_TOT / GBM);  // (16, 128)
    gemm_bias_kernel<<<ggrid, 256>>>(x, v_w, v_b, dv, M_TOT, D_MODEL, D_MODEL);

    dim3 agrid(SEQ / 64, NHEAD, BATCH);      // (32, 16, 4)
    flash_attn_tc<<<agrid, 128>>>(dv, da);

    gemm_bias_kernel<<<ggrid, 256>>>(da, o_w, o_b, out, M_TOT, D_MODEL, D_MODEL);
}